// round 1
// baseline (speedup 1.0000x reference)
#include <cuda_runtime.h>
#include <cstdint>

// Problem constants
#define NUM_DAYS 365
#define B_DIM 512
#define T_DIM 256
#define D_DIM 1024
#define D_VEC (D_DIM / 4)          // 256 float4 per row
#define ROWS (B_DIM * T_DIM)       // 131072 output rows

// Pre-fused table: Wb[day][k] = W[day][k] + b[k]. 365*1024 floats = 1.46 MB.
// Stored as float4 for vector access. __device__ global (no allocation).
__device__ float4 g_Wb[NUM_DAYS * D_VEC];

// Kernel 1: fuse bias into W once per launch (cheap: 1.46 MB r/w).
__global__ void fuse_bias_kernel(const float4* __restrict__ W4,
                                 const float4* __restrict__ b4) {
    int idx = blockIdx.x * blockDim.x + threadIdx.x;   // over NUM_DAYS*D_VEC
    if (idx < NUM_DAYS * D_VEC) {
        int col = idx & (D_VEC - 1);                   // D_VEC=256 is pow2
        float4 w = __ldg(&W4[idx]);
        float4 bb = __ldg(&b4[col]);
        w.x += bb.x; w.y += bb.y; w.z += bb.z; w.w += bb.w;
        g_Wb[idx] = w;
    }
}

// Kernel 2: gather rows. One thread per float4 of output.
// Table reads hit L2 (1.46 MB resident); output stores are streaming (__stcs)
// so the 512 MB write stream doesn't thrash the table out of L2.
__global__ void gather_kernel(const int* __restrict__ days,
                              float4* __restrict__ out4) {
    int64_t gid = (int64_t)blockIdx.x * blockDim.x + threadIdx.x;
    // gid in [0, ROWS * D_VEC)
    int row = (int)(gid >> 8);        // / D_VEC (256)
    int col = (int)(gid & 255);       // % D_VEC
    int day = __ldg(&days[row]);      // broadcast within the block's half-rows
    float4 v = __ldg(&g_Wb[day * D_VEC + col]);
    __stcs(&out4[gid], v);
}

extern "C" void kernel_launch(void* const* d_in, const int* in_sizes, int n_in,
                              void* d_out, int out_size) {
    // metadata order: days_of_year (int32 [B,T]), W (fp32 [365,D]), b (fp32 [D])
    const int*    days = (const int*)d_in[0];
    const float4* W4   = (const float4*)d_in[1];
    const float4* b4   = (const float4*)d_in[2];
    float4* out4 = (float4*)d_out;

    // 1) fuse bias into table
    {
        int n = NUM_DAYS * D_VEC;                 // 93440
        int threads = 256;
        int blocks = (n + threads - 1) / threads;
        fuse_bias_kernel<<<blocks, threads>>>(W4, b4);
    }
    // 2) gather: ROWS * D_VEC = 33,554,432 float4 stores
    {
        int64_t total = (int64_t)ROWS * D_VEC;
        int threads = 256;
        int blocks = (int)(total / threads);      // exact: 131072 blocks
        gather_kernel<<<blocks, threads>>>(days, out4);
    }
}